// round 14
// baseline (speedup 1.0000x reference)
#include <cuda_runtime.h>
#include <cuda_fp16.h>
#include <mma.h>
#include <cstdint>
#include <cstddef>

using namespace nvcuda;

// ---------------------------------------------------------------------------
// Problem constants
// ---------------------------------------------------------------------------
#define NPOS   32768          // B*H*W*D = 1*32*32*32
#define NSTATE 16
#define DTRANK 8
#define LSEQ   32

// Scratch (device globals; no allocation allowed).
// Per-branch private buffers so the three branch pipelines can run on
// separate streams concurrently (producer->consumer stays time-local).
__device__ __half g_xh [(size_t)NPOS * 128];        // x fp16 (in-proj A)
__device__ __half g_wh [3 * 512 * 128];             // inW, fp16, (512,128) per branch
__device__ __half g_xzh[3 * (size_t)NPOS * 512];    // in-proj out per branch
__device__ __half g_xch[3 * (size_t)NPOS * 256];    // conv+silu xc per branch
__device__ __half g_w2h[3 * 128 * 256];             // xpW padded 40->128 rows, per branch
__device__ float  g_P  [3 * (size_t)NPOS * 40];     // x-proj out dbc, ldc=40, per branch
__device__ __half g_yh [(size_t)NPOS * 768];        // gated y (3 branches concat per row)
__device__ __half g_Mh [128 * 768];                 // folded (outW_t -> fcW) (128,768) fp16

// ===========================================================================
// WMMA fp16 GEMM: C[M,N] = A[M,K](fp16) @ B[N,K](fp16)^T  (fp32 accumulate)
// BM=BN=128, BK=64, 256 threads (8 warps, 64x32 each).
// OUT_HALF=1: fp16 out.  OUT_HALF=0: fp32 out + optional bias.
// ncol: valid output columns (predicated 8-wide stores).
// ===========================================================================
template<bool OUT_HALF>
__global__ void __launch_bounds__(256)
hgemm_wmma(const __half* __restrict__ A, int lda,
           const __half* __restrict__ B, int ldb,
           void* __restrict__ Cv, int ldc,
           int K, const float* __restrict__ bias, int ncol) {
    __shared__ __half As[128][72];
    __shared__ __half Bs[128][72];
    __shared__ float ebuf[8][256];

    const int tid = threadIdx.x;
    const int wid = tid >> 5;
    const int lane = tid & 31;
    const int warp_m = wid & 1;        // 64-row slab
    const int warp_n = wid >> 1;       // 32-col slab
    const int bm = blockIdx.y * 128;
    const int bn = blockIdx.x * 128;

    wmma::fragment<wmma::accumulator, 16, 16, 16, float> acc[4][2];
    #pragma unroll
    for (int i = 0; i < 4; i++)
        #pragma unroll
        for (int j = 0; j < 2; j++)
            wmma::fill_fragment(acc[i][j], 0.f);

    for (int k0 = 0; k0 < K; k0 += 64) {
        #pragma unroll
        for (int it = 0; it < 4; it++) {
            int idx = tid + it * 256;          // 0..1023
            int r = idx >> 3, c8 = idx & 7;
            *(uint4*)&As[r][c8 * 8] =
                *(const uint4*)(A + (size_t)(bm + r) * lda + k0 + c8 * 8);
            *(uint4*)&Bs[r][c8 * 8] =
                *(const uint4*)(B + (size_t)(bn + r) * ldb + k0 + c8 * 8);
        }
        __syncthreads();

        #pragma unroll
        for (int kk = 0; kk < 64; kk += 16) {
            wmma::fragment<wmma::matrix_a, 16, 16, 16, __half, wmma::row_major> af[4];
            wmma::fragment<wmma::matrix_b, 16, 16, 16, __half, wmma::col_major> bf[2];
            #pragma unroll
            for (int i = 0; i < 4; i++)
                wmma::load_matrix_sync(af[i], &As[warp_m * 64 + i * 16][kk], 72);
            #pragma unroll
            for (int j = 0; j < 2; j++)
                wmma::load_matrix_sync(bf[j], &Bs[warp_n * 32 + j * 16][kk], 72);
            #pragma unroll
            for (int i = 0; i < 4; i++)
                #pragma unroll
                for (int j = 0; j < 2; j++)
                    wmma::mma_sync(acc[i][j], af[i], bf[j], acc[i][j]);
        }
        __syncthreads();
    }

    // Epilogue via per-warp smem bounce (predicated on ncol)
    const int lr = lane >> 1;          // 0..15 row in tile
    const int lc = (lane & 1) * 8;     // 0 or 8
    #pragma unroll
    for (int i = 0; i < 4; i++)
        #pragma unroll
        for (int j = 0; j < 2; j++) {
            wmma::store_matrix_sync(ebuf[wid], acc[i][j], 16, wmma::mem_row_major);
            __syncwarp();
            const int row = bm + warp_m * 64 + i * 16 + lr;
            const int col = bn + warp_n * 32 + j * 16 + lc;
            const float* src = &ebuf[wid][lr * 16 + lc];
            if (col < ncol) {
                if (OUT_HALF) {
                    __half2 hv[4];
                    #pragma unroll
                    for (int k = 0; k < 4; k++)
                        hv[k] = __floats2half2_rn(src[2 * k], src[2 * k + 1]);
                    uint4 v;
                    v.x = *(uint32_t*)&hv[0]; v.y = *(uint32_t*)&hv[1];
                    v.z = *(uint32_t*)&hv[2]; v.w = *(uint32_t*)&hv[3];
                    *(uint4*)((__half*)Cv + (size_t)row * ldc + col) = v;
                } else {
                    float4 v0 = *(const float4*)(src);
                    float4 v1 = *(const float4*)(src + 4);
                    if (bias) {
                        float4 b0 = *(const float4*)(bias + col);
                        float4 b1 = *(const float4*)(bias + col + 4);
                        v0.x += b0.x; v0.y += b0.y; v0.z += b0.z; v0.w += b0.w;
                        v1.x += b1.x; v1.y += b1.y; v1.z += b1.z; v1.w += b1.w;
                    }
                    float* cp = (float*)Cv + (size_t)row * ldc + col;
                    *(float4*)(cp)     = v0;
                    *(float4*)(cp + 4) = v1;
                }
            }
            __syncwarp();
        }
}

// ---------------------------------------------------------------------------
// Conversion / setup kernels
// ---------------------------------------------------------------------------
__global__ void cvt_x_kernel(const float* __restrict__ x, __half* __restrict__ xh) {
    int idx = blockIdx.x * 256 + threadIdx.x;       // float4 index, total 1M
    float4 v = ((const float4*)x)[idx];
    __half2 a = __floats2half2_rn(v.x, v.y);
    __half2 b = __floats2half2_rn(v.z, v.w);
    uint2 o;
    o.x = *(uint32_t*)&a;
    o.y = *(uint32_t*)&b;
    ((uint2*)xh)[idx] = o;
}

__global__ void cvt_w_kernel(const float* __restrict__ w0, const float* __restrict__ w1,
                             const float* __restrict__ w2) {
    int idx = blockIdx.x * 256 + threadIdx.x;       // 0 .. 3*65536-1
    int t = idx >> 16;
    int e = idx & 65535;
    const float* w = (t == 0) ? w0 : (t == 1) ? w1 : w2;
    g_wh[idx] = __float2half(w[e]);
}

// xpW (40,256) -> fp16, padded to 128 rows, per branch
__global__ void build_W2_kernel(const float* __restrict__ xp0, const float* __restrict__ xp1,
                                const float* __restrict__ xp2) {
    int idx = blockIdx.x * 256 + threadIdx.x;       // 0 .. 3*32768-1
    int t = idx >> 15;
    int e = idx & 32767;
    int row = e >> 8;
    int k = e & 255;
    const float* xp = (t == 0) ? xp0 : (t == 1) ? xp1 : xp2;
    float v = (row < 40) ? xp[row * 256 + k] : 0.f;
    g_w2h[idx] = __float2half(v);
}

// ---------------------------------------------------------------------------
// Fold outW_t and fcW: M[c2][t*256+j] = sum_c fcW[c2][t*128+c]*outW_t[c][j]
// grid (24,16): both operands staged in smem; pure smem FMA inner loop.
// ---------------------------------------------------------------------------
__global__ void __launch_bounds__(256)
build_M_kernel(const float* __restrict__ fcW,
               const float* __restrict__ outW_v,
               const float* __restrict__ outW_h,
               const float* __restrict__ outW_d) {
    __shared__ float oWs[128][33];
    __shared__ float frs[8][128];

    const int t  = blockIdx.x >> 3;
    const int j0 = (blockIdx.x & 7) * 32;
    const int c2base = blockIdx.y * 8;
    const int tid = threadIdx.x;

    const float* oW = (t == 0) ? outW_v : (t == 1) ? outW_h : outW_d;

    #pragma unroll
    for (int it = 0; it < 4; it++) {
        int e = tid + it * 256;            // 0..1023 -> (row, q)
        int c = e >> 3, q = e & 7;
        float4 v = *(const float4*)(oW + c * 256 + j0 + q * 4);
        oWs[c][q * 4 + 0] = v.x; oWs[c][q * 4 + 1] = v.y;
        oWs[c][q * 4 + 2] = v.z; oWs[c][q * 4 + 3] = v.w;
    }
    {
        int r = tid >> 5, q = tid & 31;
        float4 v = *(const float4*)(fcW + (c2base + r) * 384 + t * 128 + q * 4);
        *(float4*)&frs[r][q * 4] = v;
    }
    __syncthreads();

    const int c2l = tid >> 5;          // 0..7
    const int jj  = tid & 31;          // 0..31
    float a0 = 0.f, a1 = 0.f;
    #pragma unroll 16
    for (int c = 0; c < 128; c += 2) {
        a0 += frs[c2l][c]     * oWs[c][jj];
        a1 += frs[c2l][c + 1] * oWs[c + 1][jj];
    }
    g_Mh[(c2base + c2l) * 768 + t * 256 + j0 + jj] = __float2half(a0 + a1);
}

// ---------------------------------------------------------------------------
// Depthwise causal conv (width 4) + SiLU -> xc (fp16)
// grid 1024 (sequences), block 256 (channels).
// pos(l) = (blk>>5)*sHi + (blk&31)*sLo + l*sL
// ---------------------------------------------------------------------------
__device__ __forceinline__ float silu_f(float x) {
    return x / (1.f + __expf(-x));
}

__global__ void __launch_bounds__(256)
conv_silu_kernel(const __half* __restrict__ xz, __half* __restrict__ xc,
                 const float* __restrict__ convw,  // (256,4)
                 const float* __restrict__ convb,  // (256)
                 int sHi, int sLo, int sL) {
    const int i   = threadIdx.x;
    const int blk = blockIdx.x;
    const int base = (blk >> 5) * sHi + (blk & 31) * sLo;

    const float cw0 = convw[i * 4 + 0];
    const float cw1 = convw[i * 4 + 1];
    const float cw2 = convw[i * 4 + 2];
    const float cw3 = convw[i * 4 + 3];
    const float cb  = convb[i];
    float w0 = 0.f, w1 = 0.f, w2 = 0.f;
    #pragma unroll
    for (int l = 0; l < LSEQ; l++) {
        const size_t pos = (size_t)(base + l * sL);
        float cur = __half2float(xz[pos * 512 + i]);
        float v = cb + cw0 * w0 + cw1 * w1 + cw2 * w2 + cw3 * cur;
        xc[pos * 256 + i] = __float2half(silu_f(v));
        w0 = w1; w1 = w2; w2 = cur;
    }
}

// ---------------------------------------------------------------------------
// Lean selective scan: dt-proj (fp32) + softplus + recurrence + gating.
// grid 1024, block 256, smem ~5.1KB. P has ldc=40 (float4-staged).
// ---------------------------------------------------------------------------
__global__ void __launch_bounds__(256)
mamba_scan2_kernel(const float* __restrict__ dtW,   // (256,8)
                   const float* __restrict__ dtb,   // (256)
                   const float* __restrict__ Alog,  // (256,16)
                   const float* __restrict__ Dp,    // (256)
                   const float* __restrict__ Pb,    // (NPOS,40)
                   const __half* __restrict__ xc,   // (NPOS,256)
                   const __half* __restrict__ xz,   // (NPOS,512)
                   int sHi, int sLo, int sL, int branch) {
    __shared__ float dbc_s[LSEQ][40];

    const int i   = threadIdx.x;
    const int blk = blockIdx.x;
    const int base = (blk >> 5) * sHi + (blk & 31) * sLo;

    // Stage dbc: 32 rows x 40 floats = 320 float4
    for (int idx = i; idx < LSEQ * 10; idx += 256) {
        int l = idx / 10;
        int q = idx - l * 10;
        const size_t pos = (size_t)(base + l * sL);
        *(float4*)&dbc_s[l][q * 4] = *(const float4*)(Pb + pos * 40 + q * 4);
    }
    __syncthreads();

    float Areg[NSTATE];
    #pragma unroll
    for (int n = 0; n < NSTATE; n++)
        Areg[n] = -expf(Alog[i * NSTATE + n]);

    // Structural check: A_n == (n+1)*A_0 (standard Mamba init) -> one exp/step
    bool geom = true;
    #pragma unroll
    for (int n = 0; n < NSTATE; n++)
        geom = geom && (fabsf(Areg[n] - (float)(n + 1) * Areg[0])
                        <= 1e-5f * fabsf(Areg[n]));

    float dtw[DTRANK];
    #pragma unroll
    for (int r = 0; r < DTRANK; r++) dtw[r] = dtW[i * DTRANK + r];
    const float dtbi = dtb[i];
    const float dpi  = Dp[i];

    float h[NSTATE];
    #pragma unroll
    for (int n = 0; n < NSTATE; n++) h[n] = 0.f;

    for (int l = 0; l < LSEQ; l++) {
        const size_t pos = (size_t)(base + l * sL);
        float dtv = dtbi;
        #pragma unroll
        for (int r = 0; r < DTRANK; r++) dtv += dbc_s[l][r] * dtw[r];
        dtv = (dtv > 20.f) ? dtv : __logf(1.f + __expf(dtv));

        const float u  = __half2float(xc[pos * 256 + i]);
        const float du = dtv * u;
        float y = 0.f;
        if (geom) {
            const float e1 = __expf(dtv * Areg[0]);
            float pw = 1.f;
            #pragma unroll
            for (int n = 0; n < NSTATE; n++) {
                pw *= e1;                                    // e1^(n+1)
                h[n] = pw * h[n] + du * dbc_s[l][DTRANK + n];
                y += h[n] * dbc_s[l][DTRANK + NSTATE + n];
            }
        } else {
            #pragma unroll
            for (int n = 0; n < NSTATE; n++) {
                float dA = __expf(dtv * Areg[n]);
                h[n] = dA * h[n] + du * dbc_s[l][DTRANK + n];
                y += h[n] * dbc_s[l][DTRANK + NSTATE + n];
            }
        }
        const float z  = __half2float(xz[pos * 512 + 256 + i]);
        const float yo = (y + u * dpi) * silu_f(z);
        g_yh[pos * 768 + branch * 256 + i] = __float2half(yo);
    }
}

// ---------------------------------------------------------------------------
// Host launcher — per-branch pipelines overlapped on three streams.
// Fork/join via events (captured as graph edges). Streams/events are
// host-side objects created once on the first (non-capture) call; if ANY
// creation fails, we run fully sequential on stream 0 (round-12 behavior)
// with no event API calls at all.
// ---------------------------------------------------------------------------
extern "C" void kernel_launch(void* const* d_in, const int* in_sizes, int n_in,
                              void* d_out, int out_size) {
    (void)in_sizes; (void)n_in; (void)out_size;

    const float* x   = (const float*)d_in[0];
    const float* prm[3][9];
    for (int t = 0; t < 3; t++)
        for (int k = 0; k < 9; k++)
            prm[t][k] = (const float*)d_in[1 + t * 9 + k];
    const float* fcW = (const float*)d_in[28];
    const float* fcb = (const float*)d_in[29];
    float* out = (float*)d_out;

    __half *xh, *wh, *xzh, *xch, *w2h, *yh, *Mh;
    float *P;
    cudaGetSymbolAddress((void**)&xh,  g_xh);
    cudaGetSymbolAddress((void**)&wh,  g_wh);
    cudaGetSymbolAddress((void**)&xzh, g_xzh);
    cudaGetSymbolAddress((void**)&xch, g_xch);
    cudaGetSymbolAddress((void**)&P,   g_P);
    cudaGetSymbolAddress((void**)&w2h, g_w2h);
    cudaGetSymbolAddress((void**)&yh,  g_yh);
    cudaGetSymbolAddress((void**)&Mh,  g_Mh);

    // One-time stream/event setup (host resources only)
    static cudaStream_t s1 = nullptr, s2 = nullptr;
    static cudaEvent_t evA = nullptr, evH = nullptr, evD = nullptr;
    static bool init_done = false, multi = false;
    if (!init_done) {
        bool ok = true;
        ok = ok && (cudaStreamCreateWithFlags(&s1, cudaStreamNonBlocking) == cudaSuccess);
        ok = ok && (cudaStreamCreateWithFlags(&s2, cudaStreamNonBlocking) == cudaSuccess);
        ok = ok && (cudaEventCreateWithFlags(&evA, cudaEventDisableTiming) == cudaSuccess);
        ok = ok && (cudaEventCreateWithFlags(&evH, cudaEventDisableTiming) == cudaSuccess);
        ok = ok && (cudaEventCreateWithFlags(&evD, cudaEventDisableTiming) == cudaSuccess);
        multi = ok;
        init_done = true;
    }
    cudaStream_t s0 = 0;
    cudaStream_t sB[3] = {s0, multi ? s1 : s0, multi ? s2 : s0};

    // Per-branch sequence strides:  pos = (blk>>5)*sHi + (blk&31)*sLo + l*sL
    const int sHi[3] = {  32, 1024, 1024};
    const int sLo[3] = {   1,    1,   32};
    const int sL [3] = {1024,   32,    1};

    // --- Prologue on stream 0 (needed by all branches) ---
    cvt_x_kernel<<<(NPOS * 128 / 4) / 256, 256, 0, s0>>>(x, xh);
    cvt_w_kernel<<<(3 * 65536) / 256, 256, 0, s0>>>(prm[0][0], prm[1][0], prm[2][0]);
    build_W2_kernel<<<(3 * 32768) / 256, 256, 0, s0>>>(prm[0][3], prm[1][3], prm[2][3]);
    if (multi) {
        cudaEventRecord(evA, s0);
        cudaStreamWaitEvent(sB[1], evA, 0);
        cudaStreamWaitEvent(sB[2], evA, 0);
    }

    dim3 g1(512 / 128, NPOS / 128);   // in-proj: N=512
    dim3 gp(1, NPOS / 128);           // x-proj: N=128 (40 valid)

    for (int t = 0; t < 3; t++) {
        cudaStream_t st = sB[t];
        __half* xz_t = xzh + (size_t)t * NPOS * 512;
        __half* xc_t = xch + (size_t)t * NPOS * 256;
        float*  P_t  = P   + (size_t)t * NPOS * 40;
        // xz = x @ inW_t^T  (fp16 out)
        hgemm_wmma<true><<<g1, 256, 0, st>>>(xh, 128, wh + t * 512 * 128, 128,
                                             xz_t, 512, 128, nullptr, 512);
        // xc = silu(causal_conv(xi))
        conv_silu_kernel<<<1024, 256, 0, st>>>(xz_t, xc_t, prm[t][1], prm[t][2],
                                               sHi[t], sLo[t], sL[t]);
        // dbc = xc @ xpW^T (fp32 out, only 40 cols stored, ldc=40)
        hgemm_wmma<false><<<gp, 256, 0, st>>>(xc_t, 256, w2h + t * 128 * 256, 256,
                                              P_t, 40, 256, nullptr, 40);
        // recurrence
        mamba_scan2_kernel<<<1024, 256, 0, st>>>(prm[t][4], prm[t][5], prm[t][6],
                                                 prm[t][7], P_t, xc_t, xz_t,
                                                 sHi[t], sLo[t], sL[t], t);
    }

    // build_M on stream 0 (overlaps with branch h/d tails in multi mode)
    build_M_kernel<<<dim3(24, 16), 256, 0, s0>>>(fcW, prm[0][8], prm[1][8], prm[2][8]);

    // Join branches h and d back to stream 0
    if (multi) {
        cudaEventRecord(evH, sB[1]);
        cudaEventRecord(evD, sB[2]);
        cudaStreamWaitEvent(s0, evH, 0);
        cudaStreamWaitEvent(s0, evD, 0);
    }

    // out = yh(32768,768) @ M(128,768)^T + fcb  (fp32 out, bias fused)
    dim3 g2(1, NPOS / 128);
    hgemm_wmma<false><<<g2, 256, 0, s0>>>(yh, 768, Mh, 768, out, 128, 768, fcb, 128);
}

// round 15
// speedup vs baseline: 1.0922x; 1.0922x over previous
#include <cuda_runtime.h>
#include <cuda_fp16.h>
#include <mma.h>
#include <cstdint>
#include <cstddef>

using namespace nvcuda;

// ---------------------------------------------------------------------------
// Problem constants
// ---------------------------------------------------------------------------
#define NPOS   32768          // B*H*W*D = 1*32*32*32
#define NSTATE 16
#define DTRANK 8
#define LSEQ   32

// Scratch (device globals; no allocation allowed).
// Single set of pipeline buffers — the serialized per-branch pipeline
// (GEMM -> conv -> GEMM -> scan) keeps them L2-resident between kernels.
__device__ __half g_xh [(size_t)NPOS * 128];   // x fp16 (in-proj A)
__device__ __half g_wh [3 * 512 * 128];        // inW, fp16, (512,128) per branch
__device__ __half g_xzh[(size_t)NPOS * 512];   // in-proj out (xi | z), fp16
__device__ __half g_xch[(size_t)NPOS * 256];   // conv+silu xc, fp16
__device__ __half g_w2h[3 * 128 * 256];        // xpW padded 40->128 rows, per branch
__device__ float  g_P  [(size_t)NPOS * 40];    // x-proj out dbc, ldc=40
__device__ __half g_yh [(size_t)NPOS * 768];   // gated y (3 branches concat per row)
__device__ __half g_Mh [128 * 768];            // folded (outW_t -> fcW) (128,768) fp16

// ---------------------------------------------------------------------------
// cp.async helpers (Ampere+ baseline PTX; no arch-specific instructions)
// ---------------------------------------------------------------------------
__device__ __forceinline__ void cp_async16(uint32_t dst_smem, const void* src) {
    asm volatile("cp.async.cg.shared.global [%0], [%1], 16;"
                 :: "r"(dst_smem), "l"(src));
}
__device__ __forceinline__ void cp_commit() {
    asm volatile("cp.async.commit_group;");
}
__device__ __forceinline__ void cp_wait1() {
    asm volatile("cp.async.wait_group 1;");
}

// ===========================================================================
// Double-buffered WMMA fp16 GEMM (cp.async pipeline):
//   C[M,N] = A[M,K](fp16) @ B[N,K](fp16)^T  (fp32 accumulate)
// BM=BN=128, BK=64, 256 threads (8 warps, 64x32 each).
// Dynamic smem: 2 buffers x (As 128x72 + Bs 128x72) halves = 73728 B.
// OUT_HALF=1: fp16 out.  OUT_HALF=0: fp32 out + optional bias.
// ncol: valid output columns (predicated 8-wide stores).
// ===========================================================================
#define GEMM_BUF_STRIDE 36864   // bytes per (As+Bs) buffer
#define GEMM_SMEM_TOTAL 73728

template<bool OUT_HALF>
__global__ void __launch_bounds__(256)
hgemm_db(const __half* __restrict__ A, int lda,
         const __half* __restrict__ B, int ldb,
         void* __restrict__ Cv, int ldc,
         int K, const float* __restrict__ bias, int ncol) {
    extern __shared__ char dsm[];

    const int tid = threadIdx.x;
    const int wid = tid >> 5;
    const int lane = tid & 31;
    const int warp_m = wid & 1;        // 64-row slab
    const int warp_n = wid >> 1;       // 32-col slab
    const int bm = blockIdx.y * 128;
    const int bn = blockIdx.x * 128;

    // per-thread load coordinates (4 x 16B for A, 4 x 16B for B)
    const int lr = tid >> 3;           // base row group: idx = tid + it*256
    const int lc8 = tid & 7;           // 8-half column group

    wmma::fragment<wmma::accumulator, 16, 16, 16, float> acc[4][2];
    #pragma unroll
    for (int i = 0; i < 4; i++)
        #pragma unroll
        for (int j = 0; j < 2; j++)
            wmma::fill_fragment(acc[i][j], 0.f);

    const int nch = K >> 6;

    // issue loads for chunk `ch` into buffer `buf`
    auto issue_loads = [&](int buf, int k0) {
        char* base = dsm + buf * GEMM_BUF_STRIDE;
        uint32_t as_s = (uint32_t)__cvta_generic_to_shared(base);
        uint32_t bs_s = as_s + 18432;
        #pragma unroll
        for (int it = 0; it < 4; it++) {
            int r = lr + it * 32;          // 0..127
            uint32_t doff = (uint32_t)(r * 72 + lc8 * 8) * 2;
            cp_async16(as_s + doff, A + (size_t)(bm + r) * lda + k0 + lc8 * 8);
            cp_async16(bs_s + doff, B + (size_t)(bn + r) * ldb + k0 + lc8 * 8);
        }
    };

    issue_loads(0, 0);
    cp_commit();

    for (int ch = 0; ch < nch; ch++) {
        if (ch + 1 < nch) issue_loads((ch + 1) & 1, (ch + 1) * 64);
        cp_commit();
        cp_wait1();                        // chunk ch resident
        __syncthreads();

        const __half (*As)[72] =
            reinterpret_cast<const __half(*)[72]>(dsm + (ch & 1) * GEMM_BUF_STRIDE);
        const __half (*Bs)[72] =
            reinterpret_cast<const __half(*)[72]>(dsm + (ch & 1) * GEMM_BUF_STRIDE + 18432);

        #pragma unroll
        for (int kk = 0; kk < 64; kk += 16) {
            wmma::fragment<wmma::matrix_a, 16, 16, 16, __half, wmma::row_major> af[4];
            wmma::fragment<wmma::matrix_b, 16, 16, 16, __half, wmma::col_major> bf[2];
            #pragma unroll
            for (int i = 0; i < 4; i++)
                wmma::load_matrix_sync(af[i], &As[warp_m * 64 + i * 16][kk], 72);
            #pragma unroll
            for (int j = 0; j < 2; j++)
                wmma::load_matrix_sync(bf[j], &Bs[warp_n * 32 + j * 16][kk], 72);
            #pragma unroll
            for (int i = 0; i < 4; i++)
                #pragma unroll
                for (int j = 0; j < 2; j++)
                    wmma::mma_sync(acc[i][j], af[i], bf[j], acc[i][j]);
        }
        __syncthreads();                   // buffer free for chunk ch+2
    }

    // Epilogue: reuse dead smem as per-warp bounce tiles
    float* ebuf = reinterpret_cast<float*>(dsm) + wid * 256;
    const int lr2 = lane >> 1;             // 0..15 row in tile
    const int lc2 = (lane & 1) * 8;        // 0 or 8
    #pragma unroll
    for (int i = 0; i < 4; i++)
        #pragma unroll
        for (int j = 0; j < 2; j++) {
            wmma::store_matrix_sync(ebuf, acc[i][j], 16, wmma::mem_row_major);
            __syncwarp();
            const int row = bm + warp_m * 64 + i * 16 + lr2;
            const int col = bn + warp_n * 32 + j * 16 + lc2;
            const float* src = &ebuf[lr2 * 16 + lc2];
            if (col < ncol) {
                if (OUT_HALF) {
                    __half2 hv[4];
                    #pragma unroll
                    for (int k = 0; k < 4; k++)
                        hv[k] = __floats2half2_rn(src[2 * k], src[2 * k + 1]);
                    uint4 v;
                    v.x = *(uint32_t*)&hv[0]; v.y = *(uint32_t*)&hv[1];
                    v.z = *(uint32_t*)&hv[2]; v.w = *(uint32_t*)&hv[3];
                    *(uint4*)((__half*)Cv + (size_t)row * ldc + col) = v;
                } else {
                    float4 v0 = *(const float4*)(src);
                    float4 v1 = *(const float4*)(src + 4);
                    if (bias) {
                        float4 b0 = *(const float4*)(bias + col);
                        float4 b1 = *(const float4*)(bias + col + 4);
                        v0.x += b0.x; v0.y += b0.y; v0.z += b0.z; v0.w += b0.w;
                        v1.x += b1.x; v1.y += b1.y; v1.z += b1.z; v1.w += b1.w;
                    }
                    float* cp = (float*)Cv + (size_t)row * ldc + col;
                    *(float4*)(cp)     = v0;
                    *(float4*)(cp + 4) = v1;
                }
            }
            __syncwarp();
        }
}

// ===========================================================================
// Single-buffered WMMA GEMM (static smem) — used for the small x-proj GEMM.
// Identical math/layout to round 12.
// ===========================================================================
template<bool OUT_HALF>
__global__ void __launch_bounds__(256)
hgemm_sb(const __half* __restrict__ A, int lda,
         const __half* __restrict__ B, int ldb,
         void* __restrict__ Cv, int ldc,
         int K, const float* __restrict__ bias, int ncol) {
    __shared__ __half As[128][72];
    __shared__ __half Bs[128][72];
    __shared__ float ebuf[8][256];

    const int tid = threadIdx.x;
    const int wid = tid >> 5;
    const int lane = tid & 31;
    const int warp_m = wid & 1;
    const int warp_n = wid >> 1;
    const int bm = blockIdx.y * 128;
    const int bn = blockIdx.x * 128;

    wmma::fragment<wmma::accumulator, 16, 16, 16, float> acc[4][2];
    #pragma unroll
    for (int i = 0; i < 4; i++)
        #pragma unroll
        for (int j = 0; j < 2; j++)
            wmma::fill_fragment(acc[i][j], 0.f);

    for (int k0 = 0; k0 < K; k0 += 64) {
        #pragma unroll
        for (int it = 0; it < 4; it++) {
            int idx = tid + it * 256;
            int r = idx >> 3, c8 = idx & 7;
            *(uint4*)&As[r][c8 * 8] =
                *(const uint4*)(A + (size_t)(bm + r) * lda + k0 + c8 * 8);
            *(uint4*)&Bs[r][c8 * 8] =
                *(const uint4*)(B + (size_t)(bn + r) * ldb + k0 + c8 * 8);
        }
        __syncthreads();

        #pragma unroll
        for (int kk = 0; kk < 64; kk += 16) {
            wmma::fragment<wmma::matrix_a, 16, 16, 16, __half, wmma::row_major> af[4];
            wmma::fragment<wmma::matrix_b, 16, 16, 16, __half, wmma::col_major> bf[2];
            #pragma unroll
            for (int i = 0; i < 4; i++)
                wmma::load_matrix_sync(af[i], &As[warp_m * 64 + i * 16][kk], 72);
            #pragma unroll
            for (int j = 0; j < 2; j++)
                wmma::load_matrix_sync(bf[j], &Bs[warp_n * 32 + j * 16][kk], 72);
            #pragma unroll
            for (int i = 0; i < 4; i++)
                #pragma unroll
                for (int j = 0; j < 2; j++)
                    wmma::mma_sync(acc[i][j], af[i], bf[j], acc[i][j]);
        }
        __syncthreads();
    }

    const int lr = lane >> 1;
    const int lc = (lane & 1) * 8;
    #pragma unroll
    for (int i = 0; i < 4; i++)
        #pragma unroll
        for (int j = 0; j < 2; j++) {
            wmma::store_matrix_sync(ebuf[wid], acc[i][j], 16, wmma::mem_row_major);
            __syncwarp();
            const int row = bm + warp_m * 64 + i * 16 + lr;
            const int col = bn + warp_n * 32 + j * 16 + lc;
            const float* src = &ebuf[wid][lr * 16 + lc];
            if (col < ncol) {
                if (OUT_HALF) {
                    __half2 hv[4];
                    #pragma unroll
                    for (int k = 0; k < 4; k++)
                        hv[k] = __floats2half2_rn(src[2 * k], src[2 * k + 1]);
                    uint4 v;
                    v.x = *(uint32_t*)&hv[0]; v.y = *(uint32_t*)&hv[1];
                    v.z = *(uint32_t*)&hv[2]; v.w = *(uint32_t*)&hv[3];
                    *(uint4*)((__half*)Cv + (size_t)row * ldc + col) = v;
                } else {
                    float4 v0 = *(const float4*)(src);
                    float4 v1 = *(const float4*)(src + 4);
                    if (bias) {
                        float4 b0 = *(const float4*)(bias + col);
                        float4 b1 = *(const float4*)(bias + col + 4);
                        v0.x += b0.x; v0.y += b0.y; v0.z += b0.z; v0.w += b0.w;
                        v1.x += b1.x; v1.y += b1.y; v1.z += b1.z; v1.w += b1.w;
                    }
                    float* cp = (float*)Cv + (size_t)row * ldc + col;
                    *(float4*)(cp)     = v0;
                    *(float4*)(cp + 4) = v1;
                }
            }
            __syncwarp();
        }
}

// ---------------------------------------------------------------------------
// Conversion / setup kernels
// ---------------------------------------------------------------------------
__global__ void cvt_x_kernel(const float* __restrict__ x, __half* __restrict__ xh) {
    int idx = blockIdx.x * 256 + threadIdx.x;       // float4 index, total 1M
    float4 v = ((const float4*)x)[idx];
    __half2 a = __floats2half2_rn(v.x, v.y);
    __half2 b = __floats2half2_rn(v.z, v.w);
    uint2 o;
    o.x = *(uint32_t*)&a;
    o.y = *(uint32_t*)&b;
    ((uint2*)xh)[idx] = o;
}

__global__ void cvt_w_kernel(const float* __restrict__ w0, const float* __restrict__ w1,
                             const float* __restrict__ w2) {
    int idx = blockIdx.x * 256 + threadIdx.x;       // 0 .. 3*65536-1
    int t = idx >> 16;
    int e = idx & 65535;
    const float* w = (t == 0) ? w0 : (t == 1) ? w1 : w2;
    g_wh[idx] = __float2half(w[e]);
}

// xpW (40,256) -> fp16, padded to 128 rows, per branch
__global__ void build_W2_kernel(const float* __restrict__ xp0, const float* __restrict__ xp1,
                                const float* __restrict__ xp2) {
    int idx = blockIdx.x * 256 + threadIdx.x;       // 0 .. 3*32768-1
    int t = idx >> 15;
    int e = idx & 32767;
    int row = e >> 8;
    int k = e & 255;
    const float* xp = (t == 0) ? xp0 : (t == 1) ? xp1 : xp2;
    float v = (row < 40) ? xp[row * 256 + k] : 0.f;
    g_w2h[idx] = __float2half(v);
}

// ---------------------------------------------------------------------------
// Fold outW_t and fcW: M[c2][t*256+j] = sum_c fcW[c2][t*128+c]*outW_t[c][j]
// grid (24,16): both operands staged in smem; pure smem FMA inner loop.
// ---------------------------------------------------------------------------
__global__ void __launch_bounds__(256)
build_M_kernel(const float* __restrict__ fcW,
               const float* __restrict__ outW_v,
               const float* __restrict__ outW_h,
               const float* __restrict__ outW_d) {
    __shared__ float oWs[128][33];
    __shared__ float frs[8][128];

    const int t  = blockIdx.x >> 3;
    const int j0 = (blockIdx.x & 7) * 32;
    const int c2base = blockIdx.y * 8;
    const int tid = threadIdx.x;

    const float* oW = (t == 0) ? outW_v : (t == 1) ? outW_h : outW_d;

    #pragma unroll
    for (int it = 0; it < 4; it++) {
        int e = tid + it * 256;            // 0..1023 -> (row, q)
        int c = e >> 3, q = e & 7;
        float4 v = *(const float4*)(oW + c * 256 + j0 + q * 4);
        oWs[c][q * 4 + 0] = v.x; oWs[c][q * 4 + 1] = v.y;
        oWs[c][q * 4 + 2] = v.z; oWs[c][q * 4 + 3] = v.w;
    }
    {
        int r = tid >> 5, q = tid & 31;
        float4 v = *(const float4*)(fcW + (c2base + r) * 384 + t * 128 + q * 4);
        *(float4*)&frs[r][q * 4] = v;
    }
    __syncthreads();

    const int c2l = tid >> 5;          // 0..7
    const int jj  = tid & 31;          // 0..31
    float a0 = 0.f, a1 = 0.f;
    #pragma unroll 16
    for (int c = 0; c < 128; c += 2) {
        a0 += frs[c2l][c]     * oWs[c][jj];
        a1 += frs[c2l][c + 1] * oWs[c + 1][jj];
    }
    g_Mh[(c2base + c2l) * 768 + t * 256 + j0 + jj] = __float2half(a0 + a1);
}

// ---------------------------------------------------------------------------
// Depthwise causal conv (width 4) + SiLU -> g_xch (fp16)
// grid 1024 (sequences), block 256 (channels).
// pos(l) = (blk>>5)*sHi + (blk&31)*sLo + l*sL
// ---------------------------------------------------------------------------
__device__ __forceinline__ float silu_f(float x) {
    return x / (1.f + __expf(-x));
}

__global__ void __launch_bounds__(256)
conv_silu_kernel(const float* __restrict__ convw,  // (256,4)
                 const float* __restrict__ convb,  // (256)
                 int sHi, int sLo, int sL) {
    const int i   = threadIdx.x;
    const int blk = blockIdx.x;
    const int base = (blk >> 5) * sHi + (blk & 31) * sLo;

    const float cw0 = convw[i * 4 + 0];
    const float cw1 = convw[i * 4 + 1];
    const float cw2 = convw[i * 4 + 2];
    const float cw3 = convw[i * 4 + 3];
    const float cb  = convb[i];
    float w0 = 0.f, w1 = 0.f, w2 = 0.f;
    #pragma unroll
    for (int l = 0; l < LSEQ; l++) {
        const size_t pos = (size_t)(base + l * sL);
        float cur = __half2float(g_xzh[pos * 512 + i]);
        float v = cb + cw0 * w0 + cw1 * w1 + cw2 * w2 + cw3 * cur;
        g_xch[pos * 256 + i] = __float2half(silu_f(v));
        w0 = w1; w1 = w2; w2 = cur;
    }
}

// ---------------------------------------------------------------------------
// Lean selective scan: dt-proj (fp32) + softplus + recurrence + gating.
// grid 1024, block 256, smem ~5.1KB. P has ldc=40 (float4-staged).
// ---------------------------------------------------------------------------
__global__ void __launch_bounds__(256)
mamba_scan2_kernel(const float* __restrict__ dtW,   // (256,8)
                   const float* __restrict__ dtb,   // (256)
                   const float* __restrict__ Alog,  // (256,16)
                   const float* __restrict__ Dp,    // (256)
                   int sHi, int sLo, int sL, int branch) {
    __shared__ float dbc_s[LSEQ][40];

    const int i   = threadIdx.x;
    const int blk = blockIdx.x;
    const int base = (blk >> 5) * sHi + (blk & 31) * sLo;

    // Stage dbc: 32 rows x 40 floats = 320 float4
    for (int idx = i; idx < LSEQ * 10; idx += 256) {
        int l = idx / 10;
        int q = idx - l * 10;
        const size_t pos = (size_t)(base + l * sL);
        *(float4*)&dbc_s[l][q * 4] = *(const float4*)(g_P + pos * 40 + q * 4);
    }
    __syncthreads();

    float Areg[NSTATE];
    #pragma unroll
    for (int n = 0; n < NSTATE; n++)
        Areg[n] = -expf(Alog[i * NSTATE + n]);

    // Structural check: A_n == (n+1)*A_0 (standard Mamba init) -> one exp/step
    bool geom = true;
    #pragma unroll
    for (int n = 0; n < NSTATE; n++)
        geom = geom && (fabsf(Areg[n] - (float)(n + 1) * Areg[0])
                        <= 1e-5f * fabsf(Areg[n]));

    float dtw[DTRANK];
    #pragma unroll
    for (int r = 0; r < DTRANK; r++) dtw[r] = dtW[i * DTRANK + r];
    const float dtbi = dtb[i];
    const float dpi  = Dp[i];

    float h[NSTATE];
    #pragma unroll
    for (int n = 0; n < NSTATE; n++) h[n] = 0.f;

    for (int l = 0; l < LSEQ; l++) {
        const size_t pos = (size_t)(base + l * sL);
        float dtv = dtbi;
        #pragma unroll
        for (int r = 0; r < DTRANK; r++) dtv += dbc_s[l][r] * dtw[r];
        dtv = (dtv > 20.f) ? dtv : __logf(1.f + __expf(dtv));

        const float u  = __half2float(g_xch[pos * 256 + i]);
        const float du = dtv * u;
        float y = 0.f;
        if (geom) {
            const float e1 = __expf(dtv * Areg[0]);
            float pw = 1.f;
            #pragma unroll
            for (int n = 0; n < NSTATE; n++) {
                pw *= e1;                                    // e1^(n+1)
                h[n] = pw * h[n] + du * dbc_s[l][DTRANK + n];
                y += h[n] * dbc_s[l][DTRANK + NSTATE + n];
            }
        } else {
            #pragma unroll
            for (int n = 0; n < NSTATE; n++) {
                float dA = __expf(dtv * Areg[n]);
                h[n] = dA * h[n] + du * dbc_s[l][DTRANK + n];
                y += h[n] * dbc_s[l][DTRANK + NSTATE + n];
            }
        }
        const float z  = __half2float(g_xzh[pos * 512 + 256 + i]);
        const float yo = (y + u * dpi) * silu_f(z);
        g_yh[pos * 768 + branch * 256 + i] = __float2half(yo);
    }
}

// ---------------------------------------------------------------------------
// Host launcher — single-stream per-branch pipeline (best known structure)
// ---------------------------------------------------------------------------
extern "C" void kernel_launch(void* const* d_in, const int* in_sizes, int n_in,
                              void* d_out, int out_size) {
    (void)in_sizes; (void)n_in; (void)out_size;

    const float* x   = (const float*)d_in[0];
    const float* prm[3][9];
    for (int t = 0; t < 3; t++)
        for (int k = 0; k < 9; k++)
            prm[t][k] = (const float*)d_in[1 + t * 9 + k];
    const float* fcW = (const float*)d_in[28];
    const float* fcb = (const float*)d_in[29];
    float* out = (float*)d_out;

    __half *xh, *wh, *xzh, *xch, *w2h, *yh, *Mh;
    float *P;
    cudaGetSymbolAddress((void**)&xh,  g_xh);
    cudaGetSymbolAddress((void**)&wh,  g_wh);
    cudaGetSymbolAddress((void**)&xzh, g_xzh);
    cudaGetSymbolAddress((void**)&xch, g_xch);
    cudaGetSymbolAddress((void**)&P,   g_P);
    cudaGetSymbolAddress((void**)&w2h, g_w2h);
    cudaGetSymbolAddress((void**)&yh,  g_yh);
    cudaGetSymbolAddress((void**)&Mh,  g_Mh);

    // One-time: raise dynamic smem limit for the double-buffered GEMM
    static bool attr_done = false;
    if (!attr_done) {
        cudaFuncSetAttribute(hgemm_db<true>,
                             cudaFuncAttributeMaxDynamicSharedMemorySize, GEMM_SMEM_TOTAL);
        cudaFuncSetAttribute(hgemm_db<false>,
                             cudaFuncAttributeMaxDynamicSharedMemorySize, GEMM_SMEM_TOTAL);
        attr_done = true;
    }

    // Conversions + weight folds
    cvt_x_kernel<<<(NPOS * 128 / 4) / 256, 256>>>(x, xh);
    cvt_w_kernel<<<(3 * 65536) / 256, 256>>>(prm[0][0], prm[1][0], prm[2][0]);
    build_W2_kernel<<<(3 * 32768) / 256, 256>>>(prm[0][3], prm[1][3], prm[2][3]);
    build_M_kernel<<<dim3(24, 16), 256>>>(fcW, prm[0][8], prm[1][8], prm[2][8]);

    // Per-branch sequence strides:  pos = (blk>>5)*sHi + (blk&31)*sLo + l*sL
    const int sHi[3] = {  32, 1024, 1024};
    const int sLo[3] = {   1,    1,   32};
    const int sL [3] = {1024,   32,    1};

    dim3 g1(512 / 128, NPOS / 128);   // in-proj: N=512
    dim3 gp(1, NPOS / 128);           // x-proj: N=128 (40 valid)
    for (int t = 0; t < 3; t++) {
        // xz = x @ inW_t^T  (fp16 out, double-buffered)
        hgemm_db<true><<<g1, 256, GEMM_SMEM_TOTAL>>>(xh, 128, wh + t * 512 * 128, 128,
                                                     xzh, 512, 128, nullptr, 512);
        // xc = silu(causal_conv(xi))
        conv_silu_kernel<<<1024, 256>>>(prm[t][1], prm[t][2], sHi[t], sLo[t], sL[t]);
        // dbc = xc @ xpW^T (fp32 out, only 40 cols stored, ldc=40)
        hgemm_sb<false><<<gp, 256>>>(xch, 256, w2h + t * 128 * 256, 256,
                                     P, 40, 256, nullptr, 40);
        // recurrence
        mamba_scan2_kernel<<<1024, 256>>>(prm[t][4], prm[t][5], prm[t][6], prm[t][7],
                                          sHi[t], sLo[t], sL[t], t);
    }

    // out = yh(32768,768) @ M(128,768)^T + fcb  (fp32 out, bias fused, double-buffered)
    dim3 g2(1, NPOS / 128);
    hgemm_db<false><<<g2, 256, GEMM_SMEM_TOTAL>>>(yh, 768, Mh, 768, out, 128, 768, fcb, 128);
}